// round 13
// baseline (speedup 1.0000x reference)
#include <cuda_runtime.h>
#include <cuda_bf16.h>
#include <cstdint>

#define BB 64
#define SS 512
#define DD 1024
#define HH 1024
#define TT 9
#define NC 16        // time chunks per batch (chunk c = steps [32c, 32c+31], chunk0 = 1..31)
#define HS 4         // h-splits for weff
#define HSL (HH / HS)

// Scratch (device globals; no allocation allowed)
__device__ float g_Wpart[HS * TT * DD];  // per-split partial WeffT, SoA [t][d]
__device__ float g_beffp[HS * TT];       // per-split partial beff
__device__ float g_P[BB * NC * 81];      // per-chunk 9x9 log-domain composite
__device__ float g_res[BB];              // per-batch (logz - score)
__device__ unsigned g_count;             // combine completion ticket (resets to 0)

// ---------------------------------------------------------------------------
// Kernel 1: split-K Weff partials (unchanged from R9).
// ---------------------------------------------------------------------------
__global__ __launch_bounds__(256) void weff_part_kernel(
    const float* __restrict__ W1, const float* __restrict__ b1,
    const float* __restrict__ W2, const float* __restrict__ b2)
{
    __shared__ float sW2[HSL * TT];      // 9 KB slice
    int tid = threadIdx.x;
    int bx = blockIdx.x;
    int hs = (bx < 128) ? (bx & 3) : (bx - 128);
    int h0 = hs * HSL;

    {   // stage slice: 2304 floats = 576 float4
        const float4* src4 = (const float4*)(W2 + (size_t)h0 * TT);
        float4* dst = (float4*)sW2;
        for (int i = tid; i < 576; i += 256) dst[i] = src4[i];
    }
    __syncthreads();

    int w = tid >> 5, lane = tid & 31;

    if (bx < 128) {
        int dg = bx >> 2;
        int d0 = dg * 32 + w * 4;
        const float* w1p = W1 + (size_t)d0 * HH + h0;

        float acc[4][TT];
#pragma unroll
        for (int r = 0; r < 4; r++)
#pragma unroll
            for (int t = 0; t < TT; t++) acc[r][t] = 0.f;

#pragma unroll
        for (int k = 0; k < 8; k++) {           // FULL unroll: 32 LDGs in flight
            int h = (k << 5) + lane;
            float a[4];
#pragma unroll
            for (int r = 0; r < 4; r++) a[r] = w1p[(size_t)r * HH + h];  // coalesced
            const float* w2r = sW2 + h * TT;
            float wv[TT];
#pragma unroll
            for (int t = 0; t < TT; t++) wv[t] = w2r[t];
#pragma unroll
            for (int r = 0; r < 4; r++)
#pragma unroll
                for (int t = 0; t < TT; t++)
                    acc[r][t] = fmaf(a[r], wv[t], acc[r][t]);
        }
#pragma unroll
        for (int r = 0; r < 4; r++)
#pragma unroll
            for (int t = 0; t < TT; t++)
#pragma unroll
                for (int o = 16; o; o >>= 1)
                    acc[r][t] += __shfl_xor_sync(0xffffffffu, acc[r][t], o);

        if (lane < 4) {
            int d = d0 + lane;
            float* dst = g_Wpart + (size_t)hs * TT * DD;
#pragma unroll
            for (int t = 0; t < TT; t++) dst[t * DD + d] = acc[lane][t];
        }
    } else if (w == 0) {
        float acc[TT];
#pragma unroll
        for (int t = 0; t < TT; t++) acc[t] = 0.f;
#pragma unroll
        for (int k = 0; k < 8; k++) {
            int h = (k << 5) + lane;
            float a = b1[h0 + h];
            const float* r = sW2 + h * TT;
#pragma unroll
            for (int t = 0; t < TT; t++) acc[t] = fmaf(a, r[t], acc[t]);
        }
#pragma unroll
        for (int t = 0; t < TT; t++)
#pragma unroll
            for (int o = 16; o; o >>= 1)
                acc[t] += __shfl_xor_sync(0xffffffffu, acc[t], o);
        if (lane == 0) {
#pragma unroll
            for (int t = 0; t < TT; t++)
                g_beffp[hs * TT + t] = acc[t] + ((hs == 0) ? b2[t] : 0.f);
        }
    }
}

// ---------------------------------------------------------------------------
// Kernel 2 (fused): logits tile + chunk composite. Mainloop: lane owns a
// float4 of d per iter (d = k*128 + lane*4): 4 LDG.128 + 9 LDS.128 + 144 FFMA
// per iter, 8 iters. Weight vector consumed t-sequentially (low reg pressure).
// ---------------------------------------------------------------------------
__global__ __launch_bounds__(256) void gemv_chunk_kernel(
    const float* __restrict__ input, float* __restrict__ logits,
    const int* __restrict__ mask, const float* __restrict__ trans)
{
    __shared__ float sWt[TT * DD];       // 36 KB, [t][d]
    __shared__ float s_be[TT];
    __shared__ float s_lg[32][TT];       // this block's 32 logit rows
    __shared__ int   s_mk[32];
    __shared__ float sM[8][TT][12];      // per-warp composites (padded)
    __shared__ float sSc[8];             // per-warp log-scales

    int tid = threadIdx.x;
    {   // stage Weff = p0+p1+p2+p3 (L2-broadcast across all 1024 blocks)
        const float4* p0 = (const float4*)(g_Wpart + 0 * TT * DD);
        const float4* p1 = (const float4*)(g_Wpart + 1 * TT * DD);
        const float4* p2 = (const float4*)(g_Wpart + 2 * TT * DD);
        const float4* p3 = (const float4*)(g_Wpart + 3 * TT * DD);
        float4* dst = (float4*)sWt;
#pragma unroll
        for (int i = 0; i < 9; i++) {
            int idx = i * 256 + tid;
            float4 a = p0[idx], b4 = p1[idx], c4 = p2[idx], d4 = p3[idx];
            dst[idx] = make_float4(a.x + b4.x + c4.x + d4.x,
                                   a.y + b4.y + c4.y + d4.y,
                                   a.z + b4.z + c4.z + d4.z,
                                   a.w + b4.w + c4.w + d4.w);
        }
    }
    if (tid < TT)
        s_be[tid] = g_beffp[0 * TT + tid] + g_beffp[1 * TT + tid]
                  + g_beffp[2 * TT + tid] + g_beffp[3 * TT + tid];

    int b = blockIdx.x >> 4;             // batch
    int c = blockIdx.x & 15;             // chunk
    if (tid < 32) s_mk[tid] = mask[(size_t)b * SS + c * 32 + tid];
    __syncthreads();

    int w = tid >> 5, lane = tid & 31;
    int rowbase = blockIdx.x * 32 + w * 4;
    const float4* ip4 = (const float4*)(input + (size_t)rowbase * DD);
    const float4* sWt4 = (const float4*)sWt;

    float acc[4][TT];
#pragma unroll
    for (int r = 0; r < 4; r++)
#pragma unroll
        for (int t = 0; t < TT; t++) acc[r][t] = 0.f;

#pragma unroll 2
    for (int k = 0; k < 8; k++) {
        int d4 = (k << 5) + lane;                 // float4 index; d = d4*4
        float4 x[4];
#pragma unroll
        for (int r = 0; r < 4; r++) x[r] = ip4[(size_t)r * (DD / 4) + d4];  // 512B/warp
#pragma unroll
        for (int t = 0; t < TT; t++) {
            float4 wv = sWt4[t * (DD / 4) + d4];  // LDS.128, phase-conflict-free
#pragma unroll
            for (int r = 0; r < 4; r++) {
                acc[r][t] = fmaf(x[r].x, wv.x, acc[r][t]);
                acc[r][t] = fmaf(x[r].y, wv.y, acc[r][t]);
                acc[r][t] = fmaf(x[r].z, wv.z, acc[r][t]);
                acc[r][t] = fmaf(x[r].w, wv.w, acc[r][t]);
            }
        }
    }

    // butterfly reduce each of the 36 partials across lanes
#pragma unroll
    for (int r = 0; r < 4; r++)
#pragma unroll
        for (int t = 0; t < TT; t++)
#pragma unroll
            for (int o = 16; o; o >>= 1)
                acc[r][t] += __shfl_xor_sync(0xffffffffu, acc[r][t], o);

    if (lane < 4) {
        int rl = w * 4 + lane;
        float* o = logits + (size_t)(rowbase + lane) * TT;
#pragma unroll
        for (int t = 0; t < TT; t++) {
            float v = acc[lane][t] + s_be[t];
            o[t] = v;
            s_lg[rl][t] = v;
        }
    }
    __syncthreads();

    // ================= chunk composite (unchanged) =================
    bool act = (lane < TT);
    float E[TT];
#pragma unroll
    for (int k = 0; k < TT; k++)
        E[k] = act ? __expf(trans[k * TT + lane]) : 0.f;

    int ls0 = w * 4;
    int sfirst = (c == 0 && w == 0) ? 1 : 0;     // skip global t = 0

    float R[TT];
    {   // init from first step (or identity if masked)
        int ls = ls0 + sfirst;
        bool mm = (s_mk[ls] != 0);
        float eem = act ? __expf(s_lg[ls][lane]) : 0.f;
#pragma unroll
        for (int i = 0; i < TT; i++)
            R[i] = mm ? E[i] * eem : ((act && i == lane) ? 1.f : 0.f);
    }
#pragma unroll
    for (int q = 1; q < 4; q++) {
        int ls = ls0 + ((sfirst) ? (q + 1) : q);
        if (ls >= ls0 + 4) break;                // only when sfirst==1: 3 steps
        if (s_mk[ls] != 0) {
            float eem = act ? __expf(s_lg[ls][lane]) : 0.f;
#pragma unroll
            for (int i = 0; i < TT; i++) {
                float v = R[i];
                float sum = 0.f;
#pragma unroll
                for (int k = 0; k < TT; k++)
                    sum = fmaf(__shfl_sync(0xffffffffu, v, k), E[k], sum);
                R[i] = sum * eem;
            }
        }
    }
    // per-warp renorm + store
    {
        float mx = 1e-38f;
#pragma unroll
        for (int i = 0; i < TT; i++) mx = fmaxf(mx, R[i]);
        float gm = 1e-38f;
#pragma unroll
        for (int k = 0; k < TT; k++)
            gm = fmaxf(gm, __shfl_sync(0xffffffffu, mx, k));
        float inv = __fdividef(1.f, gm);
        if (act) {
#pragma unroll
            for (int i = 0; i < TT; i++) sM[w][i][lane] = R[i] * inv;
        }
        if (lane == 0) sSc[w] = __logf(gm);
    }
    __syncthreads();

    // tree: 3 levels of linear 9x9 products (A earlier, B later)
#pragma unroll
    for (int L = 0; L < 3; L++) {
        int stride = 1 << L, npr = 4 >> L;
        if (w < npr) {
            int a = 2 * stride * w, bq = a + stride;
            float Bcol[TT];
#pragma unroll
            for (int k = 0; k < TT; k++) Bcol[k] = act ? sM[bq][k][lane] : 0.f;
            float C[TT];
            float mx = 1e-38f;
#pragma unroll
            for (int i = 0; i < TT; i++) {
                float s = 0.f;
#pragma unroll
                for (int k = 0; k < TT; k++)
                    s = fmaf(sM[a][i][k], Bcol[k], s);   // A broadcast-LDS
                C[i] = s;
                mx = fmaxf(mx, s);
            }
            float gm = 1e-38f;
#pragma unroll
            for (int k = 0; k < TT; k++)
                gm = fmaxf(gm, __shfl_sync(0xffffffffu, mx, k));
            float inv = __fdividef(1.f, gm);
            float addsc = sSc[bq] + __logf(gm);
            __syncwarp();
            if (act) {
#pragma unroll
                for (int i = 0; i < TT; i++) sM[a][i][lane] = C[i] * inv;
            }
            if (lane == 0) sSc[a] += addsc;
        }
        __syncthreads();
    }

    if (w == 0 && act) {
        float sc = sSc[0];
        float* Pp = g_P + (size_t)blockIdx.x * 81;
#pragma unroll
        for (int i = 0; i < TT; i++)
            Pp[i * TT + lane] = __logf(fmaxf(sM[0][i][lane], 1e-38f)) + sc;
    }
}

// ---------------------------------------------------------------------------
// Kernel 3: per-batch combine, LINEAR-domain tree + fused final reduce
// (unchanged from R9).
// ---------------------------------------------------------------------------
__global__ __launch_bounds__(256) void crf_combine_kernel(
    const float* __restrict__ logits, const int* __restrict__ labels,
    const int* __restrict__ mask, const float* __restrict__ start,
    const float* __restrict__ endt, const float* __restrict__ trans,
    float* __restrict__ out)
{
    __shared__ float sM[NC][TT][12];   // linear matrices (padded cols)
    __shared__ float sSc[NC];          // per-matrix log scales
    __shared__ int   s_mk[SS];
    __shared__ int   s_tg[SS];
    __shared__ float s_red[256];
    __shared__ int   s_ridx[256];
    __shared__ float s_score;

    int b = blockIdx.x, tid = threadIdx.x;
    int w = tid >> 5, lane = tid & 31;
    bool act = (lane < TT);

    for (int i = tid; i < SS; i += 256) {
        s_mk[i] = mask[(size_t)b * SS + i];
        s_tg[i] = labels[(size_t)b * SS + i];
    }

    // ---- load chunk matrices, convert to linear with per-matrix renorm ----
    const float* Pb = g_P + (size_t)b * NC * 81;
#pragma unroll
    for (int h = 0; h < 2; h++) {
        int m = w * 2 + h;
        const float* Pm = Pb + m * 81;
        float col[TT];
        float mx = -1e30f;
#pragma unroll
        for (int i = 0; i < TT; i++) {
            col[i] = act ? Pm[i * TT + lane] : -1e30f;
            mx = fmaxf(mx, col[i]);
        }
        float gm = mx;
#pragma unroll
        for (int o = 16; o; o >>= 1)
            gm = fmaxf(gm, __shfl_xor_sync(0xffffffffu, gm, o));
        if (act) {
#pragma unroll
            for (int i = 0; i < TT; i++) sM[m][i][lane] = __expf(col[i] - gm);
        }
        if (lane == 0) sSc[m] = gm;
    }
    __syncthreads();

    // ---- numerator partial + last-masked-index (each thread: t, t+256) ----
    float contrib = 0.f;
    int ridx = 0;
#pragma unroll
    for (int h = 0; h < 2; h++) {
        int t = tid + h * 256;
        if (t == 0) {
            contrib += start[s_tg[0]] + logits[(size_t)b * SS * TT + s_tg[0]];
        } else if (s_mk[t] > 0) {
            int tp = t - 1;
            while (tp > 0 && s_mk[tp] == 0) tp--;
            contrib += trans[s_tg[tp] * TT + s_tg[t]]
                     + logits[((size_t)b * SS + t) * TT + s_tg[t]];
            ridx = max(ridx, t);
        }
    }
    s_red[tid] = contrib;
    s_ridx[tid] = ridx;
    __syncthreads();
#pragma unroll
    for (int o = 128; o; o >>= 1) {
        if (tid < o) {
            s_red[tid] += s_red[tid + o];
            s_ridx[tid] = max(s_ridx[tid], s_ridx[tid + o]);
        }
        __syncthreads();
    }
    if (tid == 0) s_score = s_red[0] + endt[s_tg[s_ridx[0]]];

    // ---- tree combine: 4 levels of LINEAR 9x9 products with renorm ----
#pragma unroll
    for (int L = 0; L < 4; L++) {
        int nprod = 8 >> L, stride = 1 << L;
        if (w < nprod) {
            int a = (w * 2) * stride, bq = a + stride;
            float Bcol[TT];
#pragma unroll
            for (int k = 0; k < TT; k++) Bcol[k] = act ? sM[bq][k][lane] : 0.f;
            float C[TT];
            float mx = 1e-38f;
#pragma unroll
            for (int i = 0; i < TT; i++) {
                float s = 0.f;
#pragma unroll
                for (int k = 0; k < TT; k++)
                    s = fmaf(sM[a][i][k], Bcol[k], s);   // A broadcast-LDS
                C[i] = s;
                mx = fmaxf(mx, s);
            }
            float gm = 1e-38f;
#pragma unroll
            for (int k = 0; k < TT; k++)
                gm = fmaxf(gm, __shfl_sync(0xffffffffu, mx, k));
            float inv = __fdividef(1.f, gm);
            float addsc = sSc[bq] + __logf(gm);
            __syncwarp();
            if (act) {
#pragma unroll
                for (int i = 0; i < TT; i++) sM[a][i][lane] = C[i] * inv;
            }
            if (lane == 0) sSc[a] += addsc;
        }
        __syncthreads();
    }

    // ---- final: alpha0 (linear) @ M, logz, result ----
    if (w == 0) {
        float al = act ? (start[lane] + logits[(size_t)b * SS * TT + lane]) : -1e30f;
        float Ma = al;
#pragma unroll
        for (int o = 16; o; o >>= 1)
            Ma = fmaxf(Ma, __shfl_xor_sync(0xffffffffu, Ma, o));
        float av = __expf(al - Ma);            // 0 for inactive lanes
        float vj = 0.f;
#pragma unroll
        for (int i = 0; i < TT; i++) {
            float ai = __shfl_sync(0xffffffffu, av, i);
            vj = fmaf(ai, act ? sM[0][i][lane] : 0.f, vj);
        }
        float v = act ? (__logf(fmaxf(vj, 1e-38f)) + Ma + sSc[0] + endt[lane]) : -1e30f;
        float Mx = v;
#pragma unroll
        for (int o = 16; o; o >>= 1) Mx = fmaxf(Mx, __shfl_xor_sync(0xffffffffu, Mx, o));
        float e = __expf(v - Mx);
#pragma unroll
        for (int o = 16; o; o >>= 1) e += __shfl_xor_sync(0xffffffffu, e, o);
        if (lane == 0) g_res[b] = (Mx + __logf(e)) - s_score;
    }

    // ---- last block computes the mean (fused final) ----
    __shared__ unsigned s_ticket;
    __threadfence();
    __syncthreads();
    if (tid == 0) s_ticket = atomicAdd(&g_count, 1u);
    __syncthreads();
    if (s_ticket == BB - 1) {
        __threadfence();
        float vres = (tid < BB) ? g_res[tid] : 0.f;
        s_red[tid] = vres;
        __syncthreads();
#pragma unroll
        for (int o = 32; o; o >>= 1) {
            if (tid < o) s_red[tid] += s_red[tid + o];
            __syncthreads();
        }
        if (tid == 0) {
            out[0] = s_red[0] * (1.0f / 64.0f);
            g_count = 0;                        // reset for graph replay
        }
    }
}

// ---------------------------------------------------------------------------
extern "C" void kernel_launch(void* const* d_in, const int* in_sizes, int n_in,
                              void* d_out, int out_size)
{
    const float* input  = (const float*)d_in[0];
    const int*   labels = (const int*)  d_in[1];
    const int*   mask   = (const int*)  d_in[2];
    const float* W1     = (const float*)d_in[3];
    const float* b1     = (const float*)d_in[4];
    const float* W2     = (const float*)d_in[5];
    const float* b2     = (const float*)d_in[6];
    const float* start  = (const float*)d_in[7];
    const float* endt   = (const float*)d_in[8];
    const float* trans  = (const float*)d_in[9];

    float* out    = (float*)d_out;
    float* logits = out + 1;   // output layout: [loss, logits(B,S,T)]

    weff_part_kernel<<<132, 256>>>(W1, b1, W2, b2);
    gemv_chunk_kernel<<<BB * NC, 256>>>(input, logits, mask, trans);
    crf_combine_kernel<<<BB, 256>>>(logits, labels, mask, start, endt, trans, out);
}